// round 12
// baseline (speedup 1.0000x reference)
#include <cuda_runtime.h>
#include <cuda_fp16.h>
#include <math.h>

#define N_NODES 50000
#define N_EDGES 800000
#define IN_CH   256
#define D       64
#define NC      8
#define NBLK_SC 196         // ceil(50000/256)
#define DEG_CAP 132         // smem attn cache per warp

typedef unsigned long long u64;
typedef unsigned int u32;

// ---------------- f32x2 packed helpers ----------------------------------------
__device__ __forceinline__ u64 pk2(float lo, float hi) {
    u64 r; asm("mov.b64 %0, {%1, %2};" : "=l"(r) : "f"(lo), "f"(hi)); return r;
}
__device__ __forceinline__ void up2(u64 v, float& lo, float& hi) {
    asm("mov.b64 {%0, %1}, %2;" : "=f"(lo), "=f"(hi) : "l"(v));
}
__device__ __forceinline__ void fma2(u64& d, u64 a, u64 b) {
    asm("fma.rn.f32x2 %0, %1, %2, %0;" : "+l"(d) : "l"(a), "l"(b));
}
__device__ __forceinline__ u64 add2(u64 a, u64 b) {
    u64 r; asm("add.rn.f32x2 %0, %1, %2;" : "=l"(r) : "l"(a), "l"(b)); return r;
}
// 32-dim rank-1 update (16 u64 accs); wrow warp-uniform broadcast
__device__ __forceinline__ void rank1_32(u64* acc, float s, const float* wrow) {
    u64 s2 = pk2(s, s);
    const ulonglong2* w = reinterpret_cast<const ulonglong2*>(wrow);
#pragma unroll
    for (int t = 0; t < 8; t++) {
        ulonglong2 ww = w[t];
        fma2(acc[2*t],   s2, ww.x);
        fma2(acc[2*t+1], s2, ww.y);
    }
}
__device__ __forceinline__ float dot32(const u64* a, const float* wrow) {
    u64 s = 0ull;
    const ulonglong2* w = reinterpret_cast<const ulonglong2*>(wrow);
#pragma unroll
    for (int t = 0; t < 8; t++) {
        ulonglong2 ww = w[t];
        fma2(s, a[2*t],   ww.x);
        fma2(s, a[2*t+1], ww.y);
    }
    float lo, hi; up2(s, lo, hi); return lo + hi;
}
__device__ __forceinline__ void colupd(u64* a0, u64* a1, float s0, float s1,
                                       const float* wp) {
    u64 p0 = pk2(s0, s0), p1 = pk2(s1, s1);
    const ulonglong2* w = reinterpret_cast<const ulonglong2*>(wp);
    ulonglong2 wa = w[0], wb = w[1], wc = w[2], wd = w[3];
    fma2(a0[0], p0, wa.x); fma2(a1[0], p1, wa.x);
    fma2(a0[1], p0, wa.y); fma2(a1[1], p1, wa.y);
    fma2(a0[2], p0, wb.x); fma2(a1[2], p1, wb.x);
    fma2(a0[3], p0, wb.y); fma2(a1[3], p1, wb.y);
    fma2(a0[4], p0, wc.x); fma2(a1[4], p1, wc.x);
    fma2(a0[5], p0, wc.y); fma2(a1[5], p1, wc.y);
    fma2(a0[6], p0, wd.x); fma2(a1[6], p1, wd.x);
    fma2(a0[7], p0, wd.y); fma2(a1[7], p1, wd.y);
}
__device__ __forceinline__ float4 relu4(u64 a, u64 b) {
    float x, y, z, w; up2(a, x, y); up2(b, z, w);
    return make_float4(fmaxf(x, 0.f), fmaxf(y, 0.f), fmaxf(z, 0.f), fmaxf(w, 0.f));
}
__device__ __forceinline__ float4 raw4(u64 a, u64 b) {
    float x, y, z, w; up2(a, x, y); up2(b, z, w);
    return make_float4(x, y, z, w);
}
#define SWZ(row, c4) (((row) << 4) + ((c4) ^ ((row) & 15)))

// ---------------- scratch ------------------------------------------------------
__device__ float g_qk  [N_NODES * D];
__device__ float g_qb  [N_NODES];
__device__ u32   g_tfh [(size_t)N_EDGES * 32];  // fp16 tf, edge order (102.4MB)
__device__ int   g_eidc[N_EDGES];               // CSR-pos -> (edge id << 3) | cluster
__device__ int   g_deg [N_NODES];
__device__ int   g_off [N_NODES + 1];
__device__ int   g_cur [N_NODES];
__device__ int   g_flag[NBLK_SC];
__device__ int   g_aggr[NBLK_SC];
__device__ int   g_incl[NBLK_SC];
__device__ unsigned g_ticket;
__device__ float g_cec [NC];
__device__ float g_accN[N_NODES * D];
__device__ float g_bsc [N_NODES];
__device__ float g_fused[N_NODES * D];
__device__ float g_Wqk[D * D], g_bqk[D], g_wqb[D], g_sqb;
__device__ float g_Wvo[D * D], g_bvo[D];

// ---------------- K0: prep (fold weights) + init (zero state), merged -----------
__global__ void k_prep_init(const float* __restrict__ Wq, const float* __restrict__ bq,
                            const float* __restrict__ Wk, const float* __restrict__ bk,
                            const float* __restrict__ Wv, const float* __restrict__ bv,
                            const float* __restrict__ Wo, const float* __restrict__ bo) {
    int idx = blockIdx.x * blockDim.x + threadIdx.x;
    if (idx < N_NODES) g_deg[idx] = 0;
    if (idx < NC) g_cec[idx] = 0.f;
    if (idx < NBLK_SC) g_flag[idx] = 0;
    if (idx == 0) g_ticket = 0u;
    if (idx < D * D) {
        int t = idx >> 6, j = idx & 63;
        float s1 = 0.f, s2 = 0.f;
        for (int d = 0; d < D; d++) {
            s1 = fmaf(Wq[t * D + d], Wk[j * D + d], s1);
            s2 = fmaf(Wv[t * D + d], Wo[d * D + j], s2);
        }
        g_Wqk[t * D + j] = s1;
        g_Wvo[t * D + j] = s2;
    }
    if (idx < D) {
        int j = idx;
        float a = 0.f, b = 0.f, c = 0.f;
        for (int d = 0; d < D; d++) {
            a = fmaf(bq[d], Wk[j * D + d], a);
            b = fmaf(bv[d], Wo[d * D + j], b);
            c = fmaf(Wq[j * D + d], bk[d], c);
        }
        g_bqk[j] = a; g_bvo[j] = b; g_wqb[j] = c;
        if (idx == 0) {
            float s = 0.f;
            for (int d = 0; d < D; d++) s = fmaf(bq[d], bk[d], s);
            g_sqb = s;
        }
    }
}

__global__ void k_count(const int* __restrict__ ei) {
    int e = blockIdx.x * blockDim.x + threadIdx.x;
    if (e < N_EDGES) atomicAdd(&g_deg[ei[e]], 1);
}

// ---------------- K scan: single-pass, WARP-PARALLEL lookback --------------------
__global__ void k_scan() {
    __shared__ int s[256];
    __shared__ int sbid, sexcl;
    int t = threadIdx.x;
    if (t == 0) { sbid = (int)atomicAdd(&g_ticket, 1u); sexcl = 0; }
    __syncthreads();
    int bid = sbid;
    int i = bid * 256 + t;
    int v = (i < N_NODES) ? g_deg[i] : 0;
    s[t] = v; __syncthreads();
#pragma unroll
    for (int o = 1; o < 256; o <<= 1) {
        int xv = (t >= o) ? s[t - o] : 0;
        __syncthreads();
        s[t] += xv;
        __syncthreads();
    }
    int total = s[255];
    if (t < 32) {
        if (bid == 0) {
            if (t == 0) {
                ((volatile int*)g_incl)[0] = total;
                __threadfence();
                atomicExch(&g_flag[0], 2);
            }
        } else {
            if (t == 0) {
                ((volatile int*)g_aggr)[bid] = total;
                __threadfence();
                atomicExch(&g_flag[bid], 1);
            }
            __syncwarp();
            int excl = 0;
            int p = bid - 1;
            while (true) {
                int idx = p - t;
                int f = 0, val = 0;
                if (idx >= 0) {
                    do { f = ((volatile int*)g_flag)[idx]; } while (f == 0);
                    __threadfence();
                    val = (f == 2) ? ((volatile int*)g_incl)[idx]
                                   : ((volatile int*)g_aggr)[idx];
                }
                unsigned m = __ballot_sync(0xFFFFFFFFu, f == 2);
                int firstP = m ? (__ffs(m) - 1) : 32;
                int contrib = (idx >= 0 && t <= firstP) ? val : 0;
#pragma unroll
                for (int o = 16; o > 0; o >>= 1)
                    contrib += __shfl_xor_sync(0xFFFFFFFFu, contrib, o);
                excl += contrib;
                if (m) break;
                p -= 32;
            }
            if (t == 0) {
                ((volatile int*)g_incl)[bid] = excl + total;
                __threadfence();
                atomicExch(&g_flag[bid], 2);
                sexcl = excl;
            }
        }
    }
    __syncthreads();
    int o = sexcl + s[t] - v;
    if (i < N_NODES) { g_off[i] = o; g_cur[i] = o; }
    if (i == 0) g_off[N_NODES] = N_EDGES;
}

// ---------------- K edge1 (PROFILED @ idx 3): CHUNKED tf, low-reg ----------------
// tf computed in 2 chunks of 32 dims: acc=16 u64 regs; cluster dots accumulated
// across chunks; ea staged via smem (coalesced, conflict-free stride-5-float4).
__global__ __launch_bounds__(256, 3) void k_edge1(const float* __restrict__ ea,
                                                  const int* __restrict__ ei,
                                                  const float* __restrict__ Wt,
                                                  const float* __restrict__ bt,
                                                  const float* __restrict__ ce) {
    extern __shared__ float smem[];
    float* sW  = smem;               // 16*64 = 1024
    float* sb  = sW + 16 * D;        // 64
    float* sc  = sb + D;             // 8*64 = 512
    float* scec = sc + NC * D;       // 8
    float* sea = scec + NC;          // 256 * 20 floats (stride-5 float4, conflict-free)
    u64* su = reinterpret_cast<u64*>(sea + 256 * 20);  // 256*17 u64
    for (int t = threadIdx.x; t < 16 * D / 4; t += 256)
        reinterpret_cast<float4*>(sW)[t] = reinterpret_cast<const float4*>(Wt)[t];
    if (threadIdx.x < D) sb[threadIdx.x] = bt[threadIdx.x];
    for (int t = threadIdx.x; t < NC * D / 4; t += 256)
        reinterpret_cast<float4*>(sc)[t] = reinterpret_cast<const float4*>(ce)[t];
    if (threadIdx.x < NC) scec[threadIdx.x] = 0.f;
    // stage ea tile coalesced: 256 edges x 16 floats = 1024 float4
    {
        const float4* src = reinterpret_cast<const float4*>(ea + (size_t)blockIdx.x * 256 * 16);
#pragma unroll
        for (int k = 0; k < 4; k++) {
            int idx = threadIdx.x + k * 256;
            int erow = idx >> 2, c4 = idx & 3;
            reinterpret_cast<float4*>(sea + erow * 20)[c4] = src[idx];
        }
    }
    __syncthreads();
    int tid = threadIdx.x;
    int e = blockIdx.x * 256 + tid;   // N_EDGES % 256 == 0
    const float4* av = reinterpret_cast<const float4*>(sea + tid * 20);

    float csum[NC];
#pragma unroll
    for (int c = 0; c < NC; c++) csum[c] = 0.f;

#pragma unroll
    for (int kc = 0; kc < 2; kc++) {
        u64 acc[16];
        const u64* bb = reinterpret_cast<const u64*>(sb + kc * 32);
#pragma unroll
        for (int i = 0; i < 16; i++) acc[i] = bb[i];
#pragma unroll
        for (int jv = 0; jv < 4; jv++) {
            float4 a = av[jv];
            const float* w0 = sW + (jv * 4) * D + kc * 32;
            rank1_32(acc, a.x, w0);
            rank1_32(acc, a.y, w0 + D);
            rank1_32(acc, a.z, w0 + 2 * D);
            rank1_32(acc, a.w, w0 + 3 * D);
        }
        // relu
#pragma unroll
        for (int i = 0; i < 16; i++) {
            float lo, hi; up2(acc[i], lo, hi);
            acc[i] = pk2(fmaxf(lo, 0.f), fmaxf(hi, 0.f));
        }
        // cluster partial dots over this 32-dim chunk
#pragma unroll
        for (int c = 0; c < NC; c++)
            csum[c] += dot32(acc, sc + c * D + kc * 32);
        // fp16 convert + stage (8 u64 per chunk)
#pragma unroll
        for (int i = 0; i < 8; i++) {
            float a, b; up2(acc[2*i], a, b);
            float cc, d; up2(acc[2*i+1], cc, d);
            __half2 h0 = __floats2half2_rn(a, b);
            __half2 h1 = __floats2half2_rn(cc, d);
            u32 l0 = *reinterpret_cast<u32*>(&h0);
            u32 l1 = *reinterpret_cast<u32*>(&h1);
            su[tid * 17 + kc * 8 + i] = (u64)l0 | ((u64)l1 << 32);
        }
    }

    int bc = 0; float bv = csum[0];
#pragma unroll
    for (int c = 1; c < NC; c++) if (csum[c] > bv) { bv = csum[c]; bc = c; }

    int src = ei[e];
    atomicAdd(&scec[bc], 1.f);
    int pos = atomicAdd(&g_cur[src], 1);
    g_eidc[pos] = (e << 3) | bc;

    __syncthreads();
    u64* gout = reinterpret_cast<u64*>(g_tfh) + (size_t)blockIdx.x * 4096;
#pragma unroll
    for (int k = 0; k < 16; k++) {
        int idx = threadIdx.x + k * 256;
        int el = idx >> 4, c = idx & 15;
        gout[idx] = su[el * 17 + c];
    }
    if (threadIdx.x < NC) atomicAdd(&g_cec[threadIdx.x], scec[threadIdx.x]);
}

// ---------------- K nodeA: FUSED qk = relu(x@Wd+bd)@Wqk + bqk, qb ---------------
__global__ __launch_bounds__(256) void k_nodeA(const float* __restrict__ x,
                                               const float* __restrict__ Wd,
                                               const float* __restrict__ bd) {
    extern __shared__ float smem[];
    float* sWd = smem;                     // 256*64
    float* sWq = sWd + IN_CH * D;          // 64*64
    float* sbd = sWq + D * D;              // 64
    float* sbq = sbd + D;                  // 64
    float* swq = sbq + D;                  // 64
    float4* sx4 = reinterpret_cast<float4*>(swq + D);  // 128 x 16 float4 swizzled
    for (int t = threadIdx.x; t < IN_CH * D / 4; t += 256)
        reinterpret_cast<float4*>(sWd)[t] = reinterpret_cast<const float4*>(Wd)[t];
    for (int t = threadIdx.x; t < D * D / 4; t += 256)
        reinterpret_cast<float4*>(sWq)[t] = reinterpret_cast<const float4*>(g_Wqk)[t];
    if (threadIdx.x < D) {
        sbd[threadIdx.x] = bd[threadIdx.x];
        sbq[threadIdx.x] = g_bqk[threadIdx.x];
        swq[threadIdx.x] = g_wqb[threadIdx.x];
    }

    int wid = threadIdx.x >> 5, lane = threadIdx.x & 31;
    int q = wid & 3, grp = wid >> 2;
    int rl0 = grp * 64 + lane, rl1 = rl0 + 32;
    int sw0 = rl0 & 15;
    int r0 = blockIdx.x * 128 + rl0, r1 = blockIdx.x * 128 + rl1;

    u64 a0[8], a1[8];
    const float* wq1 = sWd + q * 16;
#pragma unroll
    for (int kc = 0; kc < 4; kc++) {
        __syncthreads();
        for (int t = threadIdx.x; t < 128 * 16; t += 256) {
            int row = t >> 4, c4 = t & 15;
            int rsrc = min(blockIdx.x * 128 + row, N_NODES - 1);
            sx4[SWZ(row, c4)] =
                reinterpret_cast<const float4*>(x + (size_t)rsrc * IN_CH + kc * 64)[c4];
        }
        __syncthreads();
        if (kc == 0) {
            const u64* bb = reinterpret_cast<const u64*>(sbd + q * 16);
#pragma unroll
            for (int k = 0; k < 8; k++) { a0[k] = bb[k]; a1[k] = bb[k]; }
        }
#pragma unroll
        for (int jv = 0; jv < 16; jv++) {
            float4 v0 = sx4[(rl0 << 4) + (jv ^ sw0)];
            float4 v1 = sx4[(rl1 << 4) + (jv ^ sw0)];
            const float* w0 = wq1 + (kc * 64 + 4 * jv) * D;
            colupd(a0, a1, v0.x, v1.x, w0);
            colupd(a0, a1, v0.y, v1.y, w0 + D);
            colupd(a0, a1, v0.z, v1.z, w0 + 2 * D);
            colupd(a0, a1, v0.w, v1.w, w0 + 3 * D);
        }
    }
    __syncthreads();
#pragma unroll
    for (int k = 0; k < 4; k++) {
        sx4[SWZ(rl0, q * 4 + k)] = relu4(a0[2*k], a0[2*k+1]);
        sx4[SWZ(rl1, q * 4 + k)] = relu4(a1[2*k], a1[2*k+1]);
    }
    __syncthreads();
    {
        const u64* bb = reinterpret_cast<const u64*>(sbq + q * 16);
#pragma unroll
        for (int k = 0; k < 8; k++) { a0[k] = bb[k]; a1[k] = bb[k]; }
    }
    float qb0 = g_sqb, qb1 = g_sqb;
    const float* wq2 = sWq + q * 16;
#pragma unroll
    for (int jv = 0; jv < 16; jv++) {
        float4 v0 = sx4[(rl0 << 4) + (jv ^ sw0)];
        float4 v1 = sx4[(rl1 << 4) + (jv ^ sw0)];
        const float* w0 = wq2 + (4 * jv) * D;
        colupd(a0, a1, v0.x, v1.x, w0);
        colupd(a0, a1, v0.y, v1.y, w0 + D);
        colupd(a0, a1, v0.z, v1.z, w0 + 2 * D);
        colupd(a0, a1, v0.w, v1.w, w0 + 3 * D);
        if (q == 0) {
            qb0 = fmaf(v0.x, swq[4*jv], fmaf(v0.y, swq[4*jv+1], fmaf(v0.z, swq[4*jv+2], fmaf(v0.w, swq[4*jv+3], qb0))));
            qb1 = fmaf(v1.x, swq[4*jv], fmaf(v1.y, swq[4*jv+1], fmaf(v1.z, swq[4*jv+2], fmaf(v1.w, swq[4*jv+3], qb1))));
        }
    }
    if (r0 < N_NODES) {
        float4* o0 = reinterpret_cast<float4*>(g_qk + (size_t)r0 * D + q * 16);
#pragma unroll
        for (int k = 0; k < 4; k++) o0[k] = raw4(a0[2*k], a0[2*k+1]);
    }
    if (r1 < N_NODES) {
        float4* o1 = reinterpret_cast<float4*>(g_qk + (size_t)r1 * D + q * 16);
#pragma unroll
        for (int k = 0; k < 4; k++) o1[k] = raw4(a1[2*k], a1[2*k+1]);
    }
    if (q == 0) {
        if (r0 < N_NODES) g_qb[r0] = qb0;
        if (r1 < N_NODES) g_qb[r1] = qb1;
    }
}

// ---------------- K gather: warp-per-node, attn in-kernel, shfl lookups ---------
__global__ __launch_bounds__(256) void k_gather() {
    __shared__ float s_attn[8][DEG_CAP];
    __shared__ int   s_ec  [8][DEG_CAP];
    int wid = threadIdx.x >> 5, lane = threadIdx.x & 31;
    int n = blockIdx.x * 8 + wid;           // grid = 6250 exact
    int off = g_off[n];
    int deg = g_off[n + 1] - off;
    int eg = lane >> 3, dg = lane & 7;

    float nne = 0.f;
#pragma unroll
    for (int c = 0; c < NC; c++) nne += (g_cec[c] > 0.f) ? 1.f : 0.f;
    float inv = 1.0f / nne;

    u64 qkd[4];
    {
        const float2* qrow = reinterpret_cast<const float2*>(g_qk + (size_t)n * D) + dg * 4;
#pragma unroll
        for (int k = 0; k < 4; k++) { float2 f = qrow[k]; qkd[k] = pk2(f.x, f.y); }
    }
    float qbn = g_qb[n];

    // Phase A: attn per edge (4 edges x 8 lanes), cache in smem
    for (int j0 = 0; j0 < deg; j0 += 4) {
        int j = j0 + eg;
        bool valid = (j < deg);
        int jj = valid ? j : (deg - 1);
        int ec = g_eidc[off + jj];
        int eid = ec >> 3;
        uint4 tv = *reinterpret_cast<const uint4*>(g_tfh + (size_t)eid * 32 + dg * 4);
        u64 dacc = 0ull;
#pragma unroll
        for (int k = 0; k < 4; k++) {
            u32 h = (&tv.x)[k];
            __half2 hh = *reinterpret_cast<const __half2*>(&h);
            float2 f = __half22float2(hh);
            fma2(dacc, pk2(f.x, f.y), qkd[k]);
        }
        float lo, hi; up2(dacc, lo, hi);
        float part = lo + hi;
        part += __shfl_xor_sync(0xFFFFFFFFu, part, 1);
        part += __shfl_xor_sync(0xFFFFFFFFu, part, 2);
        part += __shfl_xor_sync(0xFFFFFFFFu, part, 4);
        if (valid && dg == 0) {
            s_attn[wid][j] = (part + qbn) * 0.125f;
            s_ec[wid][j] = ec;
        }
    }
    __syncwarp();

    // Phase B1: per-cluster max
    float pm[NC];
#pragma unroll
    for (int c = 0; c < NC; c++) pm[c] = -3.4e38f;
    for (int j = lane; j < deg; j += 32) {
        float a = s_attn[wid][j];
        int cc = s_ec[wid][j] & 7;
#pragma unroll
        for (int c = 0; c < NC; c++) if (cc == c) pm[c] = fmaxf(pm[c], a);
    }
#pragma unroll
    for (int c = 0; c < NC; c++)
#pragma unroll
        for (int o = 16; o > 0; o >>= 1)
            pm[c] = fmaxf(pm[c], __shfl_xor_sync(0xFFFFFFFFu, pm[c], o));
    float mxL = 0.f;
#pragma unroll
    for (int c = 0; c < NC; c++) if (lane == c) mxL = pm[c];

    // Phase B2: per-cluster denom + count
    float pd[NC], pc[NC];
#pragma unroll
    for (int c = 0; c < NC; c++) { pd[c] = 0.f; pc[c] = 0.f; }
    int rounds = (deg + 31) >> 5;
    for (int r = 0; r < rounds; r++) {
        int j = r * 32 + lane;
        bool v = j < deg;
        int jj = v ? j : 0;
        float a = s_attn[wid][jj];
        int cc = s_ec[wid][jj] & 7;
        float cmv = __shfl_sync(0xFFFFFFFFu, mxL, cc);
        float ex = v ? __expf(a - cmv) : 0.f;
        float on = v ? 1.f : 0.f;
#pragma unroll
        for (int c = 0; c < NC; c++) {
            pd[c] += (cc == c) ? ex : 0.f;
            pc[c] += (cc == c) ? on : 0.f;
        }
    }
#pragma unroll
    for (int c = 0; c < NC; c++)
#pragma unroll
        for (int o = 16; o > 0; o >>= 1) {
            pd[c] += __shfl_xor_sync(0xFFFFFFFFu, pd[c], o);
            pc[c] += __shfl_xor_sync(0xFFFFFFFFu, pc[c], o);
        }

    float bsc = 0.f, svL = 0.f;
#pragma unroll
    for (int c = 0; c < NC; c++) {
        if (pc[c] > 0.f) bsc += 1.0f / pc[c];
        if (lane == c) svL = (pc[c] > 0.f) ? inv / (pd[c] * pc[c]) : 0.f;
    }
    if (lane == 0) g_bsc[n] = bsc * inv;

    // Phase C: weighted tf sum
    u64 acc[4] = {0ull, 0ull, 0ull, 0ull};
    for (int j0 = 0; j0 < deg; j0 += 4) {
        int j = j0 + eg;
        bool v = j < deg;
        int jj = v ? j : (deg - 1);
        float a = s_attn[wid][jj];
        int ec = s_ec[wid][jj];
        int cc = ec & 7;
        float cmv = __shfl_sync(0xFFFFFFFFu, mxL, cc);
        float sv  = __shfl_sync(0xFFFFFFFFu, svL, cc);
        float coef = v ? __expf(a - cmv) * sv : 0.f;
        int eid = ec >> 3;
        uint4 tv = *reinterpret_cast<const uint4*>(g_tfh + (size_t)eid * 32 + dg * 4);
        u64 cf2 = pk2(coef, coef);
#pragma unroll
        for (int k = 0; k < 4; k++) {
            u32 h = (&tv.x)[k];
            __half2 hh = *reinterpret_cast<const __half2*>(&h);
            float2 f = __half22float2(hh);
            fma2(acc[k], cf2, pk2(f.x, f.y));
        }
    }
#pragma unroll
    for (int k = 0; k < 4; k++) {
        acc[k] = add2(acc[k], __shfl_xor_sync(0xFFFFFFFFu, acc[k], 8));
        acc[k] = add2(acc[k], __shfl_xor_sync(0xFFFFFFFFu, acc[k], 16));
    }
    if (eg == 0) {
        float2* o = reinterpret_cast<float2*>(g_accN + (size_t)n * D + dg * 8);
#pragma unroll
        for (int k = 0; k < 4; k++) {
            float lo, hi; up2(acc[k], lo, hi);
            o[k] = make_float2(lo, hi);
        }
    }
}

// ---------------- K E2: fused = relu(accN @ Wvo + bvo*bsc + b_out) --------------
__global__ __launch_bounds__(256) void k_E2(const float* __restrict__ bo) {
    extern __shared__ float smem[];
    float* sW  = smem;            // 64*64
    float* sbv = sW + D * D;
    float* sbo = sbv + D;
    float4* sx4 = reinterpret_cast<float4*>(sbo + D);
    for (int t = threadIdx.x; t < D * D / 4; t += 256)
        reinterpret_cast<float4*>(sW)[t] = reinterpret_cast<const float4*>(g_Wvo)[t];
    if (threadIdx.x < D) { sbv[threadIdx.x] = g_bvo[threadIdx.x]; sbo[threadIdx.x] = bo[threadIdx.x]; }
    for (int t = threadIdx.x; t < 128 * 16; t += 256) {
        int row = t >> 4, c4 = t & 15;
        int rsrc = min(blockIdx.x * 128 + row, N_NODES - 1);
        sx4[SWZ(row, c4)] =
            reinterpret_cast<const float4*>(g_accN + (size_t)rsrc * D)[c4];
    }
    __syncthreads();
    int wid = threadIdx.x >> 5, lane = threadIdx.x & 31;
    int q = wid & 3, grp = wid >> 2;
    int rl0 = grp * 64 + lane, rl1 = rl0 + 32;
    int sw0 = rl0 & 15;
    int r0 = blockIdx.x * 128 + rl0, r1 = blockIdx.x * 128 + rl1;
    int r0c = min(r0, N_NODES - 1), r1c = min(r1, N_NODES - 1);
    float bs0 = g_bsc[r0c], bs1 = g_bsc[r1c];

    u64 a0[8], a1[8];
    const float* bvq = sbv + q * 16;
    const float* boq = sbo + q * 16;
#pragma unroll
    for (int k = 0; k < 8; k++) {
        a0[k] = pk2(fmaf(bvq[2*k], bs0, boq[2*k]), fmaf(bvq[2*k+1], bs0, boq[2*k+1]));
        a1[k] = pk2(fmaf(bvq[2*k], bs1, boq[2*k]), fmaf(bvq[2*k+1], bs1, boq[2*k+1]));
    }
    const float* wq = sW + q * 16;
#pragma unroll
    for (int jv = 0; jv < 16; jv++) {
        float4 v0 = sx4[(rl0 << 4) + (jv ^ sw0)];
        float4 v1 = sx4[(rl1 << 4) + (jv ^ sw0)];
        const float* w0 = wq + (4 * jv) * D;
        colupd(a0, a1, v0.x, v1.x, w0);
        colupd(a0, a1, v0.y, v1.y, w0 + D);
        colupd(a0, a1, v0.z, v1.z, w0 + 2 * D);
        colupd(a0, a1, v0.w, v1.w, w0 + 3 * D);
    }
    if (r0 < N_NODES) {
        float4* o0 = reinterpret_cast<float4*>(g_fused + (size_t)r0 * D + q * 16);
#pragma unroll
        for (int k = 0; k < 4; k++) o0[k] = relu4(a0[2*k], a0[2*k+1]);
    }
    if (r1 < N_NODES) {
        float4* o1 = reinterpret_cast<float4*>(g_fused + (size_t)r1 * D + q * 16);
#pragma unroll
        for (int k = 0; k < 4; k++) o1[k] = relu4(a1[2*k], a1[2*k+1]);
    }
}

// ---------------- K E3: out = x + fused @ W_up + b_up ---------------------------
__global__ __launch_bounds__(256) void k_E3(const float* __restrict__ x,
                                            const float* __restrict__ Wup,
                                            const float* __restrict__ bup,
                                            float* __restrict__ out) {
    extern __shared__ float smem[];
    float* sW = smem;                 // 64 x 128 slice
    float* sb = sW + D * 128;         // 128
    float4* sx4 = reinterpret_cast<float4*>(sb + 128);
    int gy = blockIdx.y;
    for (int t = threadIdx.x; t < D * 128 / 4; t += 256) {
        int row = t >> 5, c4 = t & 31;
        reinterpret_cast<float4*>(sW + row * 128)[c4] =
            reinterpret_cast<const float4*>(Wup + row * IN_CH + gy * 128)[c4];
    }
    if (threadIdx.x < 128) sb[threadIdx.x] = bup[gy * 128 + threadIdx.x];
    for (int t = threadIdx.x; t < 64 * 16; t += 256) {
        int row = t >> 4, c4 = t & 15;
        int rsrc = min(blockIdx.x * 64 + row, N_NODES - 1);
        sx4[SWZ(row, c4)] =
            reinterpret_cast<const float4*>(g_fused + (size_t)rsrc * D)[c4];
    }
    __syncthreads();
    int wid = threadIdx.x >> 5, lane = threadIdx.x & 31;
    int q = wid;
    int rl0 = lane, rl1 = lane + 32;
    int sw0 = lane & 15;
    int r0 = blockIdx.x * 64 + rl0, r1 = blockIdx.x * 64 + rl1;

    u64 a0[8], a1[8];
    const u64* bb = reinterpret_cast<const u64*>(sb + q * 16);
#pragma unroll
    for (int k = 0; k < 8; k++) { a0[k] = bb[k]; a1[k] = bb[k]; }

    const float* wq = sW + q * 16;
#pragma unroll
    for (int jv = 0; jv < 16; jv++) {
        float4 v0 = sx4[(rl0 << 4) + (jv ^ sw0)];
        float4 v1 = sx4[(rl1 << 4) + (jv ^ sw0)];
        const float* w0 = wq + (4 * jv) * 128;
        colupd(a0, a1, v0.x, v1.x, w0);
        colupd(a0, a1, v0.y, v1.y, w0 + 128);
        colupd(a0, a1, v0.z, v1.z, w0 + 2 * 128);
        colupd(a0, a1, v0.w, v1.w, w0 + 3 * 128);
    }
    int colbase = gy * 128 + q * 16;
    if (r0 < N_NODES) {
        const float4* xr = reinterpret_cast<const float4*>(x + (size_t)r0 * IN_CH + colbase);
        float4* o = reinterpret_cast<float4*>(out + (size_t)r0 * IN_CH + colbase);
#pragma unroll
        for (int k = 0; k < 4; k++) {
            float4 r = raw4(a0[2*k], a0[2*k+1]);
            float4 xv = xr[k];
            o[k] = make_float4(xv.x + r.x, xv.y + r.y, xv.z + r.z, xv.w + r.w);
        }
    }
    if (r1 < N_NODES) {
        const float4* xr = reinterpret_cast<const float4*>(x + (size_t)r1 * IN_CH + colbase);
        float4* o = reinterpret_cast<float4*>(out + (size_t)r1 * IN_CH + colbase);
#pragma unroll
        for (int k = 0; k < 4; k++) {
            float4 r = raw4(a1[2*k], a1[2*k+1]);
            float4 xv = xr[k];
            o[k] = make_float4(xv.x + r.x, xv.y + r.y, xv.z + r.z, xv.w + r.w);
        }
    }
}

// -------------------------------------------------------------------------------
extern "C" void kernel_launch(void* const* d_in, const int* in_sizes, int n_in,
                              void* d_out, int out_size) {
    const float* x   = (const float*)d_in[0];
    const float* ea  = (const float*)d_in[1];
    const int*   ei  = (const int*)  d_in[2];
    const float* Wd  = (const float*)d_in[3];
    const float* bd  = (const float*)d_in[4];
    const float* Wup = (const float*)d_in[5];
    const float* bup = (const float*)d_in[6];
    const float* Wt  = (const float*)d_in[7];
    const float* bt  = (const float*)d_in[8];
    const float* Wq  = (const float*)d_in[9];
    const float* bq  = (const float*)d_in[10];
    const float* Wk  = (const float*)d_in[11];
    const float* bk  = (const float*)d_in[12];
    const float* Wv  = (const float*)d_in[13];
    const float* bv  = (const float*)d_in[14];
    const float* ce  = (const float*)d_in[15];
    const float* Wo  = (const float*)d_in[16];
    const float* bo  = (const float*)d_in[17];
    float* out = (float*)d_out;

    int smA  = (IN_CH * D + D * D + 3 * D) * 4 + 128 * 64 * 4;           // ~114.7KB
    int smE1 = (16 * D + D + NC * D + NC + 256 * 20) * 4 + 256 * 17 * 8; // ~60.9KB
    int smE2 = (D * D + 2 * D) * 4 + 128 * 64 * 4;                       // ~48.5KB
    int smE3 = (D * 128 + 128) * 4 + 64 * 64 * 4;                        // ~48.5KB
    cudaFuncSetAttribute(k_nodeA, cudaFuncAttributeMaxDynamicSharedMemorySize, smA);
    cudaFuncSetAttribute(k_edge1, cudaFuncAttributeMaxDynamicSharedMemorySize, smE1);
    cudaFuncSetAttribute(k_E2,    cudaFuncAttributeMaxDynamicSharedMemorySize, smE2);
    cudaFuncSetAttribute(k_E3,    cudaFuncAttributeMaxDynamicSharedMemorySize, smE3);

    int nblk128 = (N_NODES + 127) / 128;       // 391
    k_prep_init<<<NBLK_SC, 256>>>(Wq, bq, Wk, bk, Wv, bv, Wo, bo);  // idx 0
    k_count    <<<(N_EDGES + 255) / 256, 256>>>(ei);                 // idx 1
    k_scan     <<<NBLK_SC, 256>>>();                                 // idx 2
    k_edge1    <<<N_EDGES / 256, 256, smE1>>>(ea, ei, Wt, bt, ce);   // idx 3 (PROFILED)
    k_nodeA    <<<nblk128, 256, smA>>>(x, Wd, bd);                   // idx 4
    k_gather   <<<N_NODES / 8, 256>>>();                             // idx 5
    k_E2       <<<nblk128, 256, smE2>>>(bo);                         // idx 6
    k_E3       <<<dim3((N_NODES + 63) / 64, 2), 256, smE3>>>(x, Wup, bup, out);  // idx 7
}

// round 15
// speedup vs baseline: 1.4101x; 1.4101x over previous
#include <cuda_runtime.h>
#include <cuda_fp16.h>
#include <math.h>

#define N_NODES 50000
#define N_EDGES 800000
#define IN_CH   256
#define D       64
#define NC      8
#define NBLK_SC 196         // ceil(50000/256)
#define DEG_CAP 132         // smem attn cache per warp

typedef unsigned long long u64;
typedef unsigned int u32;

// ---------------- f32x2 packed helpers ----------------------------------------
__device__ __forceinline__ u64 pk2(float lo, float hi) {
    u64 r; asm("mov.b64 %0, {%1, %2};" : "=l"(r) : "f"(lo), "f"(hi)); return r;
}
__device__ __forceinline__ void up2(u64 v, float& lo, float& hi) {
    asm("mov.b64 {%0, %1}, %2;" : "=f"(lo), "=f"(hi) : "l"(v));
}
__device__ __forceinline__ void fma2(u64& d, u64 a, u64 b) {
    asm("fma.rn.f32x2 %0, %1, %2, %0;" : "+l"(d) : "l"(a), "l"(b));
}
__device__ __forceinline__ u64 add2(u64 a, u64 b) {
    u64 r; asm("add.rn.f32x2 %0, %1, %2;" : "=l"(r) : "l"(a), "l"(b)); return r;
}
__device__ __forceinline__ void rank1_64(u64* acc, float s, const float* wrow) {
    u64 s2 = pk2(s, s);
    const ulonglong2* w = reinterpret_cast<const ulonglong2*>(wrow);
#pragma unroll
    for (int t = 0; t < 16; t++) {
        ulonglong2 ww = w[t];
        fma2(acc[2*t],   s2, ww.x);
        fma2(acc[2*t+1], s2, ww.y);
    }
}
__device__ __forceinline__ float dot64(const u64* a, const float* wrow) {
    u64 s = 0ull;
    const ulonglong2* w = reinterpret_cast<const ulonglong2*>(wrow);
#pragma unroll
    for (int t = 0; t < 16; t++) {
        ulonglong2 ww = w[t];
        fma2(s, a[2*t],   ww.x);
        fma2(s, a[2*t+1], ww.y);
    }
    float lo, hi; up2(s, lo, hi); return lo + hi;
}
__device__ __forceinline__ void colupd(u64* a0, u64* a1, float s0, float s1,
                                       const float* wp) {
    u64 p0 = pk2(s0, s0), p1 = pk2(s1, s1);
    const ulonglong2* w = reinterpret_cast<const ulonglong2*>(wp);
    ulonglong2 wa = w[0], wb = w[1], wc = w[2], wd = w[3];
    fma2(a0[0], p0, wa.x); fma2(a1[0], p1, wa.x);
    fma2(a0[1], p0, wa.y); fma2(a1[1], p1, wa.y);
    fma2(a0[2], p0, wb.x); fma2(a1[2], p1, wb.x);
    fma2(a0[3], p0, wb.y); fma2(a1[3], p1, wb.y);
    fma2(a0[4], p0, wc.x); fma2(a1[4], p1, wc.x);
    fma2(a0[5], p0, wc.y); fma2(a1[5], p1, wc.y);
    fma2(a0[6], p0, wd.x); fma2(a1[6], p1, wd.x);
    fma2(a0[7], p0, wd.y); fma2(a1[7], p1, wd.y);
}
__device__ __forceinline__ float4 relu4(u64 a, u64 b) {
    float x, y, z, w; up2(a, x, y); up2(b, z, w);
    return make_float4(fmaxf(x, 0.f), fmaxf(y, 0.f), fmaxf(z, 0.f), fmaxf(w, 0.f));
}
__device__ __forceinline__ float4 raw4(u64 a, u64 b) {
    float x, y, z, w; up2(a, x, y); up2(b, z, w);
    return make_float4(x, y, z, w);
}
#define SWZ(row, c4) (((row) << 4) + ((c4) ^ ((row) & 15)))

// ---------------- scratch ------------------------------------------------------
__device__ float g_qk  [N_NODES * D];
__device__ float g_qb  [N_NODES];
__device__ u32   g_tfh [(size_t)N_EDGES * 32];  // fp16 tf, edge order (102.4MB)
__device__ int   g_eidc[N_EDGES];               // CSR-pos -> (edge id << 3) | cluster
__device__ int   g_deg [N_NODES];
__device__ int   g_off [N_NODES + 1];
__device__ int   g_cur [N_NODES];
__device__ int   g_flag[NBLK_SC];
__device__ int   g_aggr[NBLK_SC];
__device__ int   g_incl[NBLK_SC];
__device__ unsigned g_ticket;
__device__ float g_cec [NC];
__device__ float g_accN[N_NODES * D];
__device__ float g_bsc [N_NODES];
__device__ float g_fused[N_NODES * D];
__device__ float g_Wqk[D * D], g_bqk[D], g_wqb[D], g_sqb;
__device__ float g_Wvo[D * D], g_bvo[D];

// ---------------- K0: prep (fold weights) + init (zero state), merged -----------
__global__ void k_prep_init(const float* __restrict__ Wq, const float* __restrict__ bq,
                            const float* __restrict__ Wk, const float* __restrict__ bk,
                            const float* __restrict__ Wv, const float* __restrict__ bv,
                            const float* __restrict__ Wo, const float* __restrict__ bo) {
    int idx = blockIdx.x * blockDim.x + threadIdx.x;
    if (idx < N_NODES) g_deg[idx] = 0;
    if (idx < NC) g_cec[idx] = 0.f;
    if (idx < NBLK_SC) g_flag[idx] = 0;
    if (idx == 0) g_ticket = 0u;
    if (idx < D * D) {
        int t = idx >> 6, j = idx & 63;
        float s1 = 0.f, s2 = 0.f;
        for (int d = 0; d < D; d++) {
            s1 = fmaf(Wq[t * D + d], Wk[j * D + d], s1);
            s2 = fmaf(Wv[t * D + d], Wo[d * D + j], s2);
        }
        g_Wqk[t * D + j] = s1;
        g_Wvo[t * D + j] = s2;
    }
    if (idx < D) {
        int j = idx;
        float a = 0.f, b = 0.f, c = 0.f;
        for (int d = 0; d < D; d++) {
            a = fmaf(bq[d], Wk[j * D + d], a);
            b = fmaf(bv[d], Wo[d * D + j], b);
            c = fmaf(Wq[j * D + d], bk[d], c);
        }
        g_bqk[j] = a; g_bvo[j] = b; g_wqb[j] = c;
        if (idx == 0) {
            float s = 0.f;
            for (int d = 0; d < D; d++) s = fmaf(bq[d], bk[d], s);
            g_sqb = s;
        }
    }
}

__global__ void k_count(const int* __restrict__ ei) {
    int e = blockIdx.x * blockDim.x + threadIdx.x;
    if (e < N_EDGES) atomicAdd(&g_deg[ei[e]], 1);
}

// ---------------- K scan: single-pass, WARP-PARALLEL lookback --------------------
__global__ void k_scan() {
    __shared__ int s[256];
    __shared__ int sbid, sexcl;
    int t = threadIdx.x;
    if (t == 0) { sbid = (int)atomicAdd(&g_ticket, 1u); sexcl = 0; }
    __syncthreads();
    int bid = sbid;
    int i = bid * 256 + t;
    int v = (i < N_NODES) ? g_deg[i] : 0;
    s[t] = v; __syncthreads();
#pragma unroll
    for (int o = 1; o < 256; o <<= 1) {
        int xv = (t >= o) ? s[t - o] : 0;
        __syncthreads();
        s[t] += xv;
        __syncthreads();
    }
    int total = s[255];
    if (t < 32) {
        if (bid == 0) {
            if (t == 0) {
                ((volatile int*)g_incl)[0] = total;
                __threadfence();
                atomicExch(&g_flag[0], 2);
            }
        } else {
            if (t == 0) {
                ((volatile int*)g_aggr)[bid] = total;
                __threadfence();
                atomicExch(&g_flag[bid], 1);
            }
            __syncwarp();
            int excl = 0;
            int p = bid - 1;
            while (true) {
                int idx = p - t;
                int f = 0, val = 0;
                if (idx >= 0) {
                    do { f = ((volatile int*)g_flag)[idx]; } while (f == 0);
                    __threadfence();
                    val = (f == 2) ? ((volatile int*)g_incl)[idx]
                                   : ((volatile int*)g_aggr)[idx];
                }
                unsigned m = __ballot_sync(0xFFFFFFFFu, f == 2);
                int firstP = m ? (__ffs(m) - 1) : 32;
                int contrib = (idx >= 0 && t <= firstP) ? val : 0;
#pragma unroll
                for (int o = 16; o > 0; o >>= 1)
                    contrib += __shfl_xor_sync(0xFFFFFFFFu, contrib, o);
                excl += contrib;
                if (m) break;
                p -= 32;
            }
            if (t == 0) {
                ((volatile int*)g_incl)[bid] = excl + total;
                __threadfence();
                atomicExch(&g_flag[bid], 2);
                sexcl = excl;
            }
        }
    }
    __syncthreads();
    int o = sexcl + s[t] - v;
    if (i < N_NODES) { g_off[i] = o; g_cur[i] = o; }
    if (i == 0) g_off[N_NODES] = N_EDGES;
}

// per-edge time_feat (weights warp-uniform)
__device__ __forceinline__ void edge_tf(u64* acc, const float* __restrict__ ea, int e,
                                        const float* sW, const float* sb) {
    const u64* sb2 = reinterpret_cast<const u64*>(sb);
#pragma unroll
    for (int t = 0; t < 32; t++) acc[t] = sb2[t];
    const float4* ar = reinterpret_cast<const float4*>(ea + (size_t)e * 16);
#pragma unroll
    for (int jv = 0; jv < 4; jv++) {
        float4 a = ar[jv];
        const float* w0 = sW + (jv * 4) * D;
        rank1_64(acc, a.x, w0);
        rank1_64(acc, a.y, w0 + D);
        rank1_64(acc, a.z, w0 + 2 * D);
        rank1_64(acc, a.w, w0 + 3 * D);
    }
#pragma unroll
    for (int t = 0; t < 32; t++) {
        float lo, hi; up2(acc[t], lo, hi);
        acc[t] = pk2(fmaxf(lo, 0.f), fmaxf(hi, 0.f));
    }
}

// ---------------- K edge1 (PROFILED @ idx 3): R11 body + occ=2 ------------------
// Identical to the 465us/168us version except __launch_bounds__(256, 2):
// forces 128 regs -> 2 blocks/SM (occ 25% vs 12.5%) for this latency-bound kernel.
__global__ __launch_bounds__(256, 2) void k_edge1(const float* __restrict__ ea,
                                                  const int* __restrict__ ei,
                                                  const float* __restrict__ Wt,
                                                  const float* __restrict__ bt,
                                                  const float* __restrict__ ce) {
    extern __shared__ float smem[];
    float* sW = smem;            // 16*64
    float* sb = sW + 16 * D;     // 64
    float* sc = sb + D;          // 8*64
    float* scec = sc + NC * D;   // 8
    u64* su = reinterpret_cast<u64*>(scec + NC);  // 256*17 u64 stage
    for (int t = threadIdx.x; t < 16 * D / 4; t += 256)
        reinterpret_cast<float4*>(sW)[t] = reinterpret_cast<const float4*>(Wt)[t];
    if (threadIdx.x < D) sb[threadIdx.x] = bt[threadIdx.x];
    for (int t = threadIdx.x; t < NC * D / 4; t += 256)
        reinterpret_cast<float4*>(sc)[t] = reinterpret_cast<const float4*>(ce)[t];
    if (threadIdx.x < NC) scec[threadIdx.x] = 0.f;
    __syncthreads();
    int e = blockIdx.x * 256 + threadIdx.x;   // N_EDGES % 256 == 0

    u64 tf[32];
    edge_tf(tf, ea, e, sW, sb);

    int bc = 0; float bv = dot64(tf, sc);
#pragma unroll
    for (int c = 1; c < NC; c++) {
        float s = dot64(tf, sc + c * D);
        if (s > bv) { bv = s; bc = c; }
    }

    int src = ei[e];
    atomicAdd(&scec[bc], 1.f);
    int pos = atomicAdd(&g_cur[src], 1);
    g_eidc[pos] = (e << 3) | bc;

#pragma unroll
    for (int c = 0; c < 16; c++) {
        float a, b; up2(tf[2*c], a, b);
        float cc, d; up2(tf[2*c+1], cc, d);
        __half2 h0 = __floats2half2_rn(a, b);
        __half2 h1 = __floats2half2_rn(cc, d);
        u32 l0 = *reinterpret_cast<u32*>(&h0);
        u32 l1 = *reinterpret_cast<u32*>(&h1);
        su[threadIdx.x * 17 + c] = (u64)l0 | ((u64)l1 << 32);
    }
    __syncthreads();
    u64* gout = reinterpret_cast<u64*>(g_tfh) + (size_t)blockIdx.x * 4096;
#pragma unroll
    for (int k = 0; k < 16; k++) {
        int idx = threadIdx.x + k * 256;
        int el = idx >> 4, c = idx & 15;
        gout[idx] = su[el * 17 + c];
    }
    if (threadIdx.x < NC) atomicAdd(&g_cec[threadIdx.x], scec[threadIdx.x]);
}

// ---------------- K nodeA: FUSED qk = relu(x@Wd+bd)@Wqk + bqk, qb ---------------
__global__ __launch_bounds__(256) void k_nodeA(const float* __restrict__ x,
                                               const float* __restrict__ Wd,
                                               const float* __restrict__ bd) {
    extern __shared__ float smem[];
    float* sWd = smem;                     // 256*64
    float* sWq = sWd + IN_CH * D;          // 64*64
    float* sbd = sWq + D * D;              // 64
    float* sbq = sbd + D;                  // 64
    float* swq = sbq + D;                  // 64
    float4* sx4 = reinterpret_cast<float4*>(swq + D);  // 128 x 16 float4 swizzled
    for (int t = threadIdx.x; t < IN_CH * D / 4; t += 256)
        reinterpret_cast<float4*>(sWd)[t] = reinterpret_cast<const float4*>(Wd)[t];
    for (int t = threadIdx.x; t < D * D / 4; t += 256)
        reinterpret_cast<float4*>(sWq)[t] = reinterpret_cast<const float4*>(g_Wqk)[t];
    if (threadIdx.x < D) {
        sbd[threadIdx.x] = bd[threadIdx.x];
        sbq[threadIdx.x] = g_bqk[threadIdx.x];
        swq[threadIdx.x] = g_wqb[threadIdx.x];
    }

    int wid = threadIdx.x >> 5, lane = threadIdx.x & 31;
    int q = wid & 3, grp = wid >> 2;
    int rl0 = grp * 64 + lane, rl1 = rl0 + 32;
    int sw0 = rl0 & 15;
    int r0 = blockIdx.x * 128 + rl0, r1 = blockIdx.x * 128 + rl1;

    u64 a0[8], a1[8];
    const float* wq1 = sWd + q * 16;
#pragma unroll
    for (int kc = 0; kc < 4; kc++) {
        __syncthreads();
        for (int t = threadIdx.x; t < 128 * 16; t += 256) {
            int row = t >> 4, c4 = t & 15;
            int rsrc = min(blockIdx.x * 128 + row, N_NODES - 1);
            sx4[SWZ(row, c4)] =
                reinterpret_cast<const float4*>(x + (size_t)rsrc * IN_CH + kc * 64)[c4];
        }
        __syncthreads();
        if (kc == 0) {
            const u64* bb = reinterpret_cast<const u64*>(sbd + q * 16);
#pragma unroll
            for (int k = 0; k < 8; k++) { a0[k] = bb[k]; a1[k] = bb[k]; }
        }
#pragma unroll
        for (int jv = 0; jv < 16; jv++) {
            float4 v0 = sx4[(rl0 << 4) + (jv ^ sw0)];
            float4 v1 = sx4[(rl1 << 4) + (jv ^ sw0)];
            const float* w0 = wq1 + (kc * 64 + 4 * jv) * D;
            colupd(a0, a1, v0.x, v1.x, w0);
            colupd(a0, a1, v0.y, v1.y, w0 + D);
            colupd(a0, a1, v0.z, v1.z, w0 + 2 * D);
            colupd(a0, a1, v0.w, v1.w, w0 + 3 * D);
        }
    }
    __syncthreads();
#pragma unroll
    for (int k = 0; k < 4; k++) {
        sx4[SWZ(rl0, q * 4 + k)] = relu4(a0[2*k], a0[2*k+1]);
        sx4[SWZ(rl1, q * 4 + k)] = relu4(a1[2*k], a1[2*k+1]);
    }
    __syncthreads();
    {
        const u64* bb = reinterpret_cast<const u64*>(sbq + q * 16);
#pragma unroll
        for (int k = 0; k < 8; k++) { a0[k] = bb[k]; a1[k] = bb[k]; }
    }
    float qb0 = g_sqb, qb1 = g_sqb;
    const float* wq2 = sWq + q * 16;
#pragma unroll
    for (int jv = 0; jv < 16; jv++) {
        float4 v0 = sx4[(rl0 << 4) + (jv ^ sw0)];
        float4 v1 = sx4[(rl1 << 4) + (jv ^ sw0)];
        const float* w0 = wq2 + (4 * jv) * D;
        colupd(a0, a1, v0.x, v1.x, w0);
        colupd(a0, a1, v0.y, v1.y, w0 + D);
        colupd(a0, a1, v0.z, v1.z, w0 + 2 * D);
        colupd(a0, a1, v0.w, v1.w, w0 + 3 * D);
        if (q == 0) {
            qb0 = fmaf(v0.x, swq[4*jv], fmaf(v0.y, swq[4*jv+1], fmaf(v0.z, swq[4*jv+2], fmaf(v0.w, swq[4*jv+3], qb0))));
            qb1 = fmaf(v1.x, swq[4*jv], fmaf(v1.y, swq[4*jv+1], fmaf(v1.z, swq[4*jv+2], fmaf(v1.w, swq[4*jv+3], qb1))));
        }
    }
    if (r0 < N_NODES) {
        float4* o0 = reinterpret_cast<float4*>(g_qk + (size_t)r0 * D + q * 16);
#pragma unroll
        for (int k = 0; k < 4; k++) o0[k] = raw4(a0[2*k], a0[2*k+1]);
    }
    if (r1 < N_NODES) {
        float4* o1 = reinterpret_cast<float4*>(g_qk + (size_t)r1 * D + q * 16);
#pragma unroll
        for (int k = 0; k < 4; k++) o1[k] = raw4(a1[2*k], a1[2*k+1]);
    }
    if (q == 0) {
        if (r0 < N_NODES) g_qb[r0] = qb0;
        if (r1 < N_NODES) g_qb[r1] = qb1;
    }
}

// ---------------- K gather: warp-per-node, attn in-kernel, shfl lookups ---------
__global__ __launch_bounds__(256) void k_gather() {
    __shared__ float s_attn[8][DEG_CAP];
    __shared__ int   s_ec  [8][DEG_CAP];
    int wid = threadIdx.x >> 5, lane = threadIdx.x & 31;
    int n = blockIdx.x * 8 + wid;           // grid = 6250 exact
    int off = g_off[n];
    int deg = g_off[n + 1] - off;
    int eg = lane >> 3, dg = lane & 7;

    float nne = 0.f;
#pragma unroll
    for (int c = 0; c < NC; c++) nne += (g_cec[c] > 0.f) ? 1.f : 0.f;
    float inv = 1.0f / nne;

    u64 qkd[4];
    {
        const float2* qrow = reinterpret_cast<const float2*>(g_qk + (size_t)n * D) + dg * 4;
#pragma unroll
        for (int k = 0; k < 4; k++) { float2 f = qrow[k]; qkd[k] = pk2(f.x, f.y); }
    }
    float qbn = g_qb[n];

    // Phase A: attn per edge (4 edges x 8 lanes), cache in smem
    for (int j0 = 0; j0 < deg; j0 += 4) {
        int j = j0 + eg;
        bool valid = (j < deg);
        int jj = valid ? j : (deg - 1);
        int ec = g_eidc[off + jj];
        int eid = ec >> 3;
        uint4 tv = *reinterpret_cast<const uint4*>(g_tfh + (size_t)eid * 32 + dg * 4);
        u64 dacc = 0ull;
#pragma unroll
        for (int k = 0; k < 4; k++) {
            u32 h = (&tv.x)[k];
            __half2 hh = *reinterpret_cast<const __half2*>(&h);
            float2 f = __half22float2(hh);
            fma2(dacc, pk2(f.x, f.y), qkd[k]);
        }
        float lo, hi; up2(dacc, lo, hi);
        float part = lo + hi;
        part += __shfl_xor_sync(0xFFFFFFFFu, part, 1);
        part += __shfl_xor_sync(0xFFFFFFFFu, part, 2);
        part += __shfl_xor_sync(0xFFFFFFFFu, part, 4);
        if (valid && dg == 0) {
            s_attn[wid][j] = (part + qbn) * 0.125f;
            s_ec[wid][j] = ec;
        }
    }
    __syncwarp();

    // Phase B1: per-cluster max
    float pm[NC];
#pragma unroll
    for (int c = 0; c < NC; c++) pm[c] = -3.4e38f;
    for (int j = lane; j < deg; j += 32) {
        float a = s_attn[wid][j];
        int cc = s_ec[wid][j] & 7;
#pragma unroll
        for (int c = 0; c < NC; c++) if (cc == c) pm[c] = fmaxf(pm[c], a);
    }
#pragma unroll
    for (int c = 0; c < NC; c++)
#pragma unroll
        for (int o = 16; o > 0; o >>= 1)
            pm[c] = fmaxf(pm[c], __shfl_xor_sync(0xFFFFFFFFu, pm[c], o));
    float mxL = 0.f;
#pragma unroll
    for (int c = 0; c < NC; c++) if (lane == c) mxL = pm[c];

    // Phase B2: per-cluster denom + count
    float pd[NC], pc[NC];
#pragma unroll
    for (int c = 0; c < NC; c++) { pd[c] = 0.f; pc[c] = 0.f; }
    int rounds = (deg + 31) >> 5;
    for (int r = 0; r < rounds; r++) {
        int j = r * 32 + lane;
        bool v = j < deg;
        int jj = v ? j : 0;
        float a = s_attn[wid][jj];
        int cc = s_ec[wid][jj] & 7;
        float cmv = __shfl_sync(0xFFFFFFFFu, mxL, cc);
        float ex = v ? __expf(a - cmv) : 0.f;
        float on = v ? 1.f : 0.f;
#pragma unroll
        for (int c = 0; c < NC; c++) {
            pd[c] += (cc == c) ? ex : 0.f;
            pc[c] += (cc == c) ? on : 0.f;
        }
    }
#pragma unroll
    for (int c = 0; c < NC; c++)
#pragma unroll
        for (int o = 16; o > 0; o >>= 1) {
            pd[c] += __shfl_xor_sync(0xFFFFFFFFu, pd[c], o);
            pc[c] += __shfl_xor_sync(0xFFFFFFFFu, pc[c], o);
        }

    float bsc = 0.f, svL = 0.f;
#pragma unroll
    for (int c = 0; c < NC; c++) {
        if (pc[c] > 0.f) bsc += 1.0f / pc[c];
        if (lane == c) svL = (pc[c] > 0.f) ? inv / (pd[c] * pc[c]) : 0.f;
    }
    if (lane == 0) g_bsc[n] = bsc * inv;

    // Phase C: weighted tf sum
    u64 acc[4] = {0ull, 0ull, 0ull, 0ull};
    for (int j0 = 0; j0 < deg; j0 += 4) {
        int j = j0 + eg;
        bool v = j < deg;
        int jj = v ? j : (deg - 1);
        float a = s_attn[wid][jj];
        int ec = s_ec[wid][jj];
        int cc = ec & 7;
        float cmv = __shfl_sync(0xFFFFFFFFu, mxL, cc);
        float sv  = __shfl_sync(0xFFFFFFFFu, svL, cc);
        float coef = v ? __expf(a - cmv) * sv : 0.f;
        int eid = ec >> 3;
        uint4 tv = *reinterpret_cast<const uint4*>(g_tfh + (size_t)eid * 32 + dg * 4);
        u64 cf2 = pk2(coef, coef);
#pragma unroll
        for (int k = 0; k < 4; k++) {
            u32 h = (&tv.x)[k];
            __half2 hh = *reinterpret_cast<const __half2*>(&h);
            float2 f = __half22float2(hh);
            fma2(acc[k], cf2, pk2(f.x, f.y));
        }
    }
#pragma unroll
    for (int k = 0; k < 4; k++) {
        acc[k] = add2(acc[k], __shfl_xor_sync(0xFFFFFFFFu, acc[k], 8));
        acc[k] = add2(acc[k], __shfl_xor_sync(0xFFFFFFFFu, acc[k], 16));
    }
    if (eg == 0) {
        float2* o = reinterpret_cast<float2*>(g_accN + (size_t)n * D + dg * 8);
#pragma unroll
        for (int k = 0; k < 4; k++) {
            float lo, hi; up2(acc[k], lo, hi);
            o[k] = make_float2(lo, hi);
        }
    }
}

// ---------------- K E2: fused = relu(accN @ Wvo + bvo*bsc + b_out) --------------
__global__ __launch_bounds__(256) void k_E2(const float* __restrict__ bo) {
    extern __shared__ float smem[];
    float* sW  = smem;            // 64*64
    float* sbv = sW + D * D;
    float* sbo = sbv + D;
    float4* sx4 = reinterpret_cast<float4*>(sbo + D);
    for (int t = threadIdx.x; t < D * D / 4; t += 256)
        reinterpret_cast<float4*>(sW)[t] = reinterpret_cast<const float4*>(g_Wvo)[t];
    if (threadIdx.x < D) { sbv[threadIdx.x] = g_bvo[threadIdx.x]; sbo[threadIdx.x] = bo[threadIdx.x]; }
    for (int t = threadIdx.x; t < 128 * 16; t += 256) {
        int row = t >> 4, c4 = t & 15;
        int rsrc = min(blockIdx.x * 128 + row, N_NODES - 1);
        sx4[SWZ(row, c4)] =
            reinterpret_cast<const float4*>(g_accN + (size_t)rsrc * D)[c4];
    }
    __syncthreads();
    int wid = threadIdx.x >> 5, lane = threadIdx.x & 31;
    int q = wid & 3, grp = wid >> 2;
    int rl0 = grp * 64 + lane, rl1 = rl0 + 32;
    int sw0 = rl0 & 15;
    int r0 = blockIdx.x * 128 + rl0, r1 = blockIdx.x * 128 + rl1;
    int r0c = min(r0, N_NODES - 1), r1c = min(r1, N_NODES - 1);
    float bs0 = g_bsc[r0c], bs1 = g_bsc[r1c];

    u64 a0[8], a1[8];
    const float* bvq = sbv + q * 16;
    const float* boq = sbo + q * 16;
#pragma unroll
    for (int k = 0; k < 8; k++) {
        a0[k] = pk2(fmaf(bvq[2*k], bs0, boq[2*k]), fmaf(bvq[2*k+1], bs0, boq[2*k+1]));
        a1[k] = pk2(fmaf(bvq[2*k], bs1, boq[2*k]), fmaf(bvq[2*k+1], bs1, boq[2*k+1]));
    }
    const float* wq = sW + q * 16;
#pragma unroll
    for (int jv = 0; jv < 16; jv++) {
        float4 v0 = sx4[(rl0 << 4) + (jv ^ sw0)];
        float4 v1 = sx4[(rl1 << 4) + (jv ^ sw0)];
        const float* w0 = wq + (4 * jv) * D;
        colupd(a0, a1, v0.x, v1.x, w0);
        colupd(a0, a1, v0.y, v1.y, w0 + D);
        colupd(a0, a1, v0.z, v1.z, w0 + 2 * D);
        colupd(a0, a1, v0.w, v1.w, w0 + 3 * D);
    }
    if (r0 < N_NODES) {
        float4* o0 = reinterpret_cast<float4*>(g_fused + (size_t)r0 * D + q * 16);
#pragma unroll
        for (int k = 0; k < 4; k++) o0[k] = relu4(a0[2*k], a0[2*k+1]);
    }
    if (r1 < N_NODES) {
        float4* o1 = reinterpret_cast<float4*>(g_fused + (size_t)r1 * D + q * 16);
#pragma unroll
        for (int k = 0; k < 4; k++) o1[k] = relu4(a1[2*k], a1[2*k+1]);
    }
}

// ---------------- K E3: out = x + fused @ W_up + b_up ---------------------------
__global__ __launch_bounds__(256) void k_E3(const float* __restrict__ x,
                                            const float* __restrict__ Wup,
                                            const float* __restrict__ bup,
                                            float* __restrict__ out) {
    extern __shared__ float smem[];
    float* sW = smem;                 // 64 x 128 slice
    float* sb = sW + D * 128;         // 128
    float4* sx4 = reinterpret_cast<float4*>(sb + 128);
    int gy = blockIdx.y;
    for (int t = threadIdx.x; t < D * 128 / 4; t += 256) {
        int row = t >> 5, c4 = t & 31;
        reinterpret_cast<float4*>(sW + row * 128)[c4] =
            reinterpret_cast<const float4*>(Wup + row * IN_CH + gy * 128)[c4];
    }
    if (threadIdx.x < 128) sb[threadIdx.x] = bup[gy * 128 + threadIdx.x];
    for (int t = threadIdx.x; t < 64 * 16; t += 256) {
        int row = t >> 4, c4 = t & 15;
        int rsrc = min(blockIdx.x * 64 + row, N_NODES - 1);
        sx4[SWZ(row, c4)] =
            reinterpret_cast<const float4*>(g_fused + (size_t)rsrc * D)[c4];
    }
    __syncthreads();
    int wid = threadIdx.x >> 5, lane = threadIdx.x & 31;
    int q = wid;
    int rl0 = lane, rl1 = lane + 32;
    int sw0 = lane & 15;
    int r0 = blockIdx.x * 64 + rl0, r1 = blockIdx.x * 64 + rl1;

    u64 a0[8], a1[8];
    const u64* bb = reinterpret_cast<const u64*>(sb + q * 16);
#pragma unroll
    for (int k = 0; k < 8; k++) { a0[k] = bb[k]; a1[k] = bb[k]; }

    const float* wq = sW + q * 16;
#pragma unroll
    for (int jv = 0; jv < 16; jv++) {
        float4 v0 = sx4[(rl0 << 4) + (jv ^ sw0)];
        float4 v1 = sx4[(rl1 << 4) + (jv ^ sw0)];
        const float* w0 = wq + (4 * jv) * 128;
        colupd(a0, a1, v0.x, v1.x, w0);
        colupd(a0, a1, v0.y, v1.y, w0 + 128);
        colupd(a0, a1, v0.z, v1.z, w0 + 2 * 128);
        colupd(a0, a1, v0.w, v1.w, w0 + 3 * 128);
    }
    int colbase = gy * 128 + q * 16;
    if (r0 < N_NODES) {
        const float4* xr = reinterpret_cast<const float4*>(x + (size_t)r0 * IN_CH + colbase);
        float4* o = reinterpret_cast<float4*>(out + (size_t)r0 * IN_CH + colbase);
#pragma unroll
        for (int k = 0; k < 4; k++) {
            float4 r = raw4(a0[2*k], a0[2*k+1]);
            float4 xv = xr[k];
            o[k] = make_float4(xv.x + r.x, xv.y + r.y, xv.z + r.z, xv.w + r.w);
        }
    }
    if (r1 < N_NODES) {
        const float4* xr = reinterpret_cast<const float4*>(x + (size_t)r1 * IN_CH + colbase);
        float4* o = reinterpret_cast<float4*>(out + (size_t)r1 * IN_CH + colbase);
#pragma unroll
        for (int k = 0; k < 4; k++) {
            float4 r = raw4(a1[2*k], a1[2*k+1]);
            float4 xv = xr[k];
            o[k] = make_float4(xv.x + r.x, xv.y + r.y, xv.z + r.z, xv.w + r.w);
        }
    }
}

// -------------------------------------------------------------------------------
extern "C" void kernel_launch(void* const* d_in, const int* in_sizes, int n_in,
                              void* d_out, int out_size) {
    const float* x   = (const float*)d_in[0];
    const float* ea  = (const float*)d_in[1];
    const int*   ei  = (const int*)  d_in[2];
    const float* Wd  = (const float*)d_in[3];
    const float* bd  = (const float*)d_in[4];
    const float* Wup = (const float*)d_in[5];
    const float* bup = (const float*)d_in[6];
    const float* Wt  = (const float*)d_in[7];
    const float* bt  = (const float*)d_in[8];
    const float* Wq  = (const float*)d_in[9];
    const float* bq  = (const float*)d_in[10];
    const float* Wk  = (const float*)d_in[11];
    const float* bk  = (const float*)d_in[12];
    const float* Wv  = (const float*)d_in[13];
    const float* bv  = (const float*)d_in[14];
    const float* ce  = (const float*)d_in[15];
    const float* Wo  = (const float*)d_in[16];
    const float* bo  = (const float*)d_in[17];
    float* out = (float*)d_out;

    int smA  = (IN_CH * D + D * D + 3 * D) * 4 + 128 * 64 * 4;   // ~114.7KB
    int smE1 = (16 * D + D + NC * D + NC) * 4 + 256 * 17 * 8;    // ~41.2KB
    int smE2 = (D * D + 2 * D) * 4 + 128 * 64 * 4;               // ~48.5KB
    int smE3 = (D * 128 + 128) * 4 + 64 * 64 * 4;                // ~48.5KB
    cudaFuncSetAttribute(k_nodeA, cudaFuncAttributeMaxDynamicSharedMemorySize, smA);
    cudaFuncSetAttribute(k_edge1, cudaFuncAttributeMaxDynamicSharedMemorySize, smE1);
    cudaFuncSetAttribute(k_E2,    cudaFuncAttributeMaxDynamicSharedMemorySize, smE2);
    cudaFuncSetAttribute(k_E3,    cudaFuncAttributeMaxDynamicSharedMemorySize, smE3);

    int nblk128 = (N_NODES + 127) / 128;       // 391
    k_prep_init<<<NBLK_SC, 256>>>(Wq, bq, Wk, bk, Wv, bv, Wo, bo);  // idx 0
    k_count    <<<(N_EDGES + 255) / 256, 256>>>(ei);                 // idx 1
    k_scan     <<<NBLK_SC, 256>>>();                                 // idx 2
    k_edge1    <<<N_EDGES / 256, 256, smE1>>>(ea, ei, Wt, bt, ce);   // idx 3 (PROFILED)
    k_nodeA    <<<nblk128, 256, smA>>>(x, Wd, bd);                   // idx 4
    k_gather   <<<N_NODES / 8, 256>>>();                             // idx 5
    k_E2       <<<nblk128, 256, smE2>>>(bo);                         // idx 6
    k_E3       <<<dim3((N_NODES + 63) / 64, 2), 256, smE3>>>(x, Wup, bup, out);  // idx 7
}